// round 11
// baseline (speedup 1.0000x reference)
#include <cuda_runtime.h>
#include <cuda_fp16.h>
#include <stdint.h>
#include <math.h>

#define Bt 32
#define Ct 684
#define Ht 16
#define Wt 64
#define HWt 1024
#define HIDt 256
#define At 512
#define NPATCH 121
#define KCOMB 805
#define NST 13
#define NPOS 32768
#define NCTA 148
#define NTHR 320
#define ALPHA_OFF (Bt*Ct)
#define ASUM_OFF  (Bt*Ct + Bt*HWt)

// dynamic smem: Xbuf[2]@0 (32768) | Wbuf[2]@32768 (65536) | stg[2]@98304 (2*33792) | asum@165888 (4096)
#define XB  0
#define WB  32768
#define STG 98304
#define STGB 33792
#define ASM 165888
#define SMEM_SZ 169984
#define XT 16384
#define WT 32768
#define STGP 132
#define NTILE 512

// ---------------- device scratch ----------------
__device__ __align__(1024) unsigned char g_W[(size_t)2 * NST * WT];
__device__ float g_Weff[At * NPATCH];
__device__ float g_query[Bt * At];
__device__ float g_Epart[2 * NPOS];
__device__ int g_cnt[2];

// ---------------- helpers ----------------
__device__ __forceinline__ uint32_t smem_u32(const void* p) {
    uint32_t a;
    asm("{ .reg .u64 t; cvta.to.shared.u64 t, %1; cvt.u32.u64 %0, t; }" : "=r"(a) : "l"(p));
    return a;
}
__device__ __forceinline__ void mb_init(uint32_t a, uint32_t c) {
    asm volatile("mbarrier.init.shared.b64 [%0], %1;" :: "r"(a), "r"(c) : "memory");
}
__device__ __forceinline__ void mb_arrive(uint32_t a) {
    asm volatile("mbarrier.arrive.shared.b64 _, [%0];" :: "r"(a) : "memory");
}
__device__ __forceinline__ void mb_tx(uint32_t a, uint32_t bytes) {
    asm volatile("mbarrier.arrive.expect_tx.shared.b64 _, [%0], %1;" :: "r"(a), "r"(bytes) : "memory");
}
__device__ __forceinline__ void mb_wait(uint32_t a, uint32_t par) {
    uint32_t d = 0;
    while (!d)
        asm volatile("{ .reg .pred p; mbarrier.try_wait.parity.acquire.cta.shared::cta.b64 p,[%1],%2,0x989680; selp.b32 %0,1,0,p; }"
                     : "=r"(d) : "r"(a), "r"(par) : "memory");
}
__device__ __forceinline__ void blkcp(uint32_t dst, const void* src, uint32_t bytes, uint32_t mbar) {
    asm volatile("cp.async.bulk.shared::cta.global.mbarrier::complete_tx::bytes [%0], [%1], %2, [%3];"
                 :: "r"(dst), "l"(src), "r"(bytes), "r"(mbar) : "memory");
}
__device__ __forceinline__ void cpa16(uint32_t dst, const void* src) {
    asm volatile("cp.async.cg.shared.global [%0], [%1], 16;" :: "r"(dst), "l"(src));
}
#define BARS(id, n) asm volatile("bar.sync %0, %1;" :: "r"(id), "r"(n) : "memory")
#define LDMX4(r0,r1,r2,r3,addr) \
    asm volatile("ldmatrix.sync.aligned.m8n8.x4.shared.b16 {%0,%1,%2,%3}, [%4];" \
                 : "=r"(r0),"=r"(r1),"=r"(r2),"=r"(r3) : "r"(addr))
#define MMA(d,a,b) \
    asm volatile("mma.sync.aligned.m16n8k16.row.col.f32.f16.f16.f32 " \
                 "{%0,%1,%2,%3},{%4,%5,%6,%7},{%8,%9},{%0,%1,%2,%3};" \
                 : "+f"(d[0]),"+f"(d[1]),"+f"(d[2]),"+f"(d[3]) \
                 : "r"(a[0]),"r"(a[1]),"r"(a[2]),"r"(a[3]),"r"(b[0]),"r"(b[1]))

__device__ __forceinline__ uint32_t h2u(float v0, float v1) {
    __half2 h = __floats2half2_rn(v0, v1);
    return *(uint32_t*)&h;
}
__device__ __forceinline__ float ftanh(float x) {
    float e = __expf(2.0f * x);
    return 1.0f - __fdividef(2.0f, e + 1.0f);
}
__device__ __forceinline__ void gridbar(int ph) {
    __syncthreads();
    if (threadIdx.x == 0) {
        __threadfence();
        atomicAdd(&g_cnt[ph], 1);
        while (atomicAdd(&g_cnt[ph], 0) < NCTA) { }
        __threadfence();
    }
    __syncthreads();
}

// ---------------- prep: merged weff (y=0) + query (y=1) ----------------
__global__ void k_small(const float* __restrict__ Waw, const float* __restrict__ Wac,
                        const float* __restrict__ hidden, const float* __restrict__ Wh,
                        const float* __restrict__ bh, const float* __restrict__ bec) {
    if (blockIdx.y == 0) {
        int a = blockIdx.x, j = threadIdx.x;
        if (j >= NPATCH) return;
        float s = 0.f;
        for (int c = 0; c < At; ++c) s = fmaf(Waw[a * At + c], Wac[c * NPATCH + j], s);
        g_Weff[a * NPATCH + j] = s;
    } else {
        int b = blockIdx.x, tid = threadIdx.x;
        if (b >= Bt) return;
        __shared__ float h[HIDt];
        for (int k = tid; k < HIDt; k += 128) h[k] = hidden[b * HIDt + k];
        __syncthreads();
        for (int a = tid; a < At; a += 128) {
            const float* wr = Wh + a * HIDt;
            float s = 0.f;
            #pragma unroll 8
            for (int k = 0; k < HIDt; ++k) s = fmaf(wr[k], h[k], s);
            g_query[b * At + a] = s + bh[a] + bec[a];
        }
    }
}

// ---------------- prep: W tiles [ag][s] 256a x 64k fp16, SW128-swizzled ----------------
__global__ void k_wpack(const float* __restrict__ Wec) {
    __shared__ float sm[64][129];
    const int s = blockIdx.x, ag = blockIdx.y, tid = threadIdx.x;
    const int w = tid >> 5, lane = tid & 31;
    #pragma unroll 4
    for (int i = 0; i < 32; ++i) {
        int kk = lane + (i & 1) * 32;
        int a = w + (i >> 1) * 8;
        int k = s * 64 + kk, aa = ag * 128 + a;
        float v = 0.f;
        if (k < Ct) v = Wec[aa * Ct + k];
        else if (k < KCOMB) v = g_Weff[aa * NPATCH + (k - Ct)];
        sm[kk][a] = v;
    }
    __syncthreads();
    unsigned char* tile = g_W + ((size_t)((ag >> 1) * NST + s) << 15);
    const int rbase = (ag & 1) * 128;
    #pragma unroll
    for (int i = 0; i < 4; ++i) {
        int idx = i * 256 + tid;
        int r = idx >> 3, ch = idx & 7;
        uint32_t hv[4];
        #pragma unroll
        for (int j = 0; j < 4; ++j)
            hv[j] = h2u(sm[ch * 8 + 2 * j][r], sm[ch * 8 + 2 * j + 1][r]);
        int r2 = rbase + r;
        uint32_t off = r2 * 128 + ((ch ^ (r2 & 7)) << 4);
        *(uint4*)(tile + off) = make_uint4(hv[0], hv[1], hv[2], hv[3]);
    }
}

__global__ void k_zero() {
    if (threadIdx.x < 2) g_cnt[threadIdx.x] = 0;
}

// ---------------- main: warp-specialized persistent megakernel ----------------
__global__ __launch_bounds__(NTHR, 1)
void k_mma(const float* __restrict__ cnn, const float* __restrict__ asum,
           const float* __restrict__ mask, const float* __restrict__ Wv,
           const float* __restrict__ bv, float* __restrict__ out) {
    extern __shared__ char dsm[];
    __shared__ float qs[256], ws[256], esm[512], wred[16];
    __shared__ __align__(8) uint64_t mbars[6];   // fullW[2], fullX[2], empty[2]
    const uint32_t sb = smem_u32(dsm);
    const uint32_t mFW = smem_u32(&mbars[0]);
    const uint32_t mFX = mFW + 16;
    const uint32_t mEM = mFW + 32;
    float* asm_s = (float*)(dsm + ASM);
    const int tid = threadIdx.x, lane = tid & 31, w = tid >> 5;

    if (tid == 0) {
        mb_init(mFW, 1);      mb_init(mFW + 8, 1);
        mb_init(mFX, 64);     mb_init(mFX + 8, 64);
        mb_init(mEM, 8);      mb_init(mEM + 8, 8);
    }
    __syncthreads();

    int tiles[4], ntiles = 0;
    for (int t = blockIdx.x; t < NTILE; t += NCTA) tiles[ntiles++] = t;
    const int total = ntiles * NST;

    if (w >= 8) {
        // ================= PRODUCER (warps 8-9, 64 threads) =================
        const int ptid = tid - 256;

        auto cpaX = [&](int g) {
            int ti2 = g / NST, s2 = g - ti2 * NST, bx = tiles[ti2] >> 1;
            int b2 = bx >> 3, pos0b = (bx & 7) * 128;
            const float* src = cnn + ((size_t)b2 * Ct + s2 * 64) * HWt + pos0b;
            uint32_t dstb = sb + STG + (g & 1) * STGB;
            #pragma unroll
            for (int i = 0; i < 32; ++i) {
                int id = i * 64 + ptid;
                int row = id >> 5, c = id & 31;
                if (s2 * 64 + row < Ct)
                    cpa16(dstb + row * (STGP * 4) + c * 16,
                          (const char*)(src + (size_t)row * HWt) + c * 16);
            }
        };
        auto convert = [&](int g) {
            int ti2 = g / NST, s2 = g - ti2 * NST, bx = tiles[ti2] >> 1;
            int pos0b = (bx & 7) * 128;
            float* stgf = (float*)(dsm + STG + (g & 1) * STGB);
            char* dx = dsm + XB + (g & 1) * XT;
            const int k0 = s2 * 64;
            if (k0 + 63 < Ct) {
                #pragma unroll
                for (int i = 0; i < 16; ++i) {
                    int idx = i * 64 + ptid;
                    int r = idx & 127, ch = idx >> 7;
                    uint32_t hv[4];
                    #pragma unroll
                    for (int j = 0; j < 4; ++j)
                        hv[j] = h2u(stgf[(ch * 8 + 2 * j) * STGP + r],
                                    stgf[(ch * 8 + 2 * j + 1) * STGP + r]);
                    uint32_t off = r * 128 + ((ch ^ (r & 7)) << 4);
                    *(uint4*)(dx + off) = make_uint4(hv[0], hv[1], hv[2], hv[3]);
                }
            } else {
                #pragma unroll
                for (int i = 0; i < 16; ++i) {
                    int idx = i * 64 + ptid;
                    int r = idx & 127, ch = idx >> 7;
                    float v[8];
                    #pragma unroll
                    for (int jj = 0; jj < 8; ++jj) {
                        int kk = ch * 8 + jj, k = k0 + kk;
                        float x = 0.f;
                        if (k < Ct) {
                            x = stgf[kk * STGP + r];
                        } else if (k < KCOMB) {
                            int j = k - Ct;
                            int pos = pos0b + r;
                            int hh = (pos >> 6) + j / 11 - 5;
                            int ww = (pos & 63) + j % 11 - 5;
                            if (hh >= 0 && hh < Ht && ww >= 0 && ww < Wt) x = asm_s[hh * Wt + ww];
                        }
                        v[jj] = x;
                    }
                    uint32_t hv[4];
                    #pragma unroll
                    for (int j = 0; j < 4; ++j) hv[j] = h2u(v[2 * j], v[2 * j + 1]);
                    uint32_t off = r * 128 + ((ch ^ (r & 7)) << 4);
                    *(uint4*)(dx + off) = make_uint4(hv[0], hv[1], hv[2], hv[3]);
                }
            }
        };

        cpaX(0);
        asm volatile("cp.async.commit_group;" ::: "memory");
        if (total > 1) cpaX(1);
        asm volatile("cp.async.commit_group;" ::: "memory");

        for (int g = 0; g < total; ++g) {
            const int slot = g & 1;
            if (g >= 2) mb_wait(mEM + slot * 8, ((g - 2) >> 1) & 1);
            if (ptid == 0) {
                int ti2 = g / NST, s2 = g - ti2 * NST, by = tiles[ti2] & 1;
                mb_tx(mFW + slot * 8, WT);
                blkcp(sb + WB + slot * WT, g_W + ((size_t)(by * NST + s2) << 15), WT, mFW + slot * 8);
            }
            asm volatile("cp.async.wait_group 1;" ::: "memory");
            if (g % NST == 0) {
                int nb = (tiles[g / NST] >> 1) >> 3;
                for (int i = ptid; i < HWt; i += 64) asm_s[i] = asum[nb * HWt + i];
            }
            BARS(2, 64);
            convert(g);
            mb_arrive(mFX + slot * 8);
            if (g + 2 < total) cpaX(g + 2);
            asm volatile("cp.async.commit_group;" ::: "memory");
        }
    } else {
        // ================= CONSUMER (warps 0-7, 256 threads) =================
        const int wm = w >> 2, wn = w & 3;
        float acc[4][8][4];
        #pragma unroll
        for (int mt = 0; mt < 4; ++mt)
            #pragma unroll
            for (int nt = 0; nt < 8; ++nt)
                #pragma unroll
                for (int r = 0; r < 4; ++r) acc[mt][nt][r] = 0.f;

        int ti = 0, s = 0;
        for (int g = 0; g < total; ++g) {
            const int slot = g & 1, ph = (g >> 1) & 1;
            mb_wait(mFW + slot * 8, ph);
            mb_wait(mFX + slot * 8, ph);
            const uint32_t xb = sb + XB + slot * XT;
            const uint32_t wb = sb + WB + slot * WT;
            #pragma unroll
            for (int ks = 0; ks < 4; ++ks) {
                uint32_t bf[8][2];
                const int browb = wn * 64 + (lane & 7) + ((lane >> 4) & 1) * 8;
                const int bc = 2 * ks + ((lane >> 3) & 1);
                #pragma unroll
                for (int np = 0; np < 4; ++np) {
                    int r = browb + np * 16;
                    uint32_t boff = r * 128 + ((bc ^ (r & 7)) << 4);
                    LDMX4(bf[np*2][0], bf[np*2][1], bf[np*2+1][0], bf[np*2+1][1], wb + boff);
                }
                const int arow = wm * 64 + (lane & 15);
                const int ac = 2 * ks + (lane >> 4);
                #pragma unroll
                for (int mt = 0; mt < 4; ++mt) {
                    int r = arow + mt * 16;
                    uint32_t aoff = r * 128 + ((ac ^ (r & 7)) << 4);
                    uint32_t af[4];
                    LDMX4(af[0], af[1], af[2], af[3], xb + aoff);
                    #pragma unroll
                    for (int nt = 0; nt < 8; ++nt)
                        MMA(acc[mt][nt], af, bf[nt]);
                }
            }
            if (lane == 0) mb_arrive(mEM + slot * 8);

            if (++s == NST) {
                const int bx = tiles[ti] >> 1, by = tiles[ti] & 1;
                const int pos0 = bx * 128, a0 = by * 256, b = bx >> 3;
                qs[tid] = g_query[b * At + a0 + tid];
                ws[tid] = Wv[a0 + tid];
                BARS(1, 256);
                #pragma unroll
                for (int mt = 0; mt < 4; ++mt) {
                    float er0 = 0.f, er1 = 0.f;
                    #pragma unroll
                    for (int nt = 0; nt < 8; ++nt) {
                        int col = wn * 64 + nt * 8 + (lane & 3) * 2;
                        float q0 = qs[col], q1 = qs[col + 1];
                        float w0 = ws[col], w1 = ws[col + 1];
                        er0 = fmaf(w0, ftanh(acc[mt][nt][0] + q0), er0);
                        er0 = fmaf(w1, ftanh(acc[mt][nt][1] + q1), er0);
                        er1 = fmaf(w0, ftanh(acc[mt][nt][2] + q0), er1);
                        er1 = fmaf(w1, ftanh(acc[mt][nt][3] + q1), er1);
                    }
                    er0 += __shfl_xor_sync(0xffffffffu, er0, 1);
                    er0 += __shfl_xor_sync(0xffffffffu, er0, 2);
                    er1 += __shfl_xor_sync(0xffffffffu, er1, 1);
                    er1 += __shfl_xor_sync(0xffffffffu, er1, 2);
                    if ((lane & 3) == 0) {
                        int r = wm * 64 + mt * 16 + (lane >> 2);
                        esm[r * 4 + wn] = er0;
                        esm[(r + 8) * 4 + wn] = er1;
                    }
                }
                BARS(1, 256);
                if (tid < 128)
                    g_Epart[by * NPOS + pos0 + tid] =
                        esm[tid * 4] + esm[tid * 4 + 1] + esm[tid * 4 + 2] + esm[tid * 4 + 3];
                BARS(1, 256);
                #pragma unroll
                for (int mt = 0; mt < 4; ++mt)
                    #pragma unroll
                    for (int nt = 0; nt < 8; ++nt)
                        #pragma unroll
                        for (int r = 0; r < 4; ++r) acc[mt][nt][r] = 0.f;
                s = 0; ++ti;
            }
        }
    }

    // ==== all Epart written ====
    gridbar(0);

    // softmax per batch (CTAs 0-31), 320 threads
    if (blockIdx.x < Bt) {
        const int b = blockIdx.x;
        float* exs = (float*)dsm;
        float bvv = bv[0];
        float m = -1e30f;
        for (int p = tid; p < HWt; p += NTHR) {
            float e = bvv + g_Epart[b * HWt + p] + g_Epart[NPOS + b * HWt + p];
            exs[p] = e;
            m = fmaxf(m, e);
        }
        #pragma unroll
        for (int o = 16; o > 0; o >>= 1) m = fmaxf(m, __shfl_xor_sync(0xffffffffu, m, o));
        if (lane == 0) wred[w] = m;
        __syncthreads();
        if (w == 0) {
            float v = (lane < 10) ? wred[lane] : -1e30f;
            #pragma unroll
            for (int o = 16; o > 0; o >>= 1) v = fmaxf(v, __shfl_xor_sync(0xffffffffu, v, o));
            if (lane == 0) wred[10] = v;
        }
        __syncthreads();
        m = wred[10];
        float ls = 0.f;
        for (int p = tid; p < HWt; p += NTHR) {
            float v = expf(exs[p] - m) * mask[b * HWt + p];
            exs[p] = v;
            ls += v;
        }
        __syncthreads();   // exs rewrite done before reduce reads? (reduce uses regs; sync for wred reuse)
        #pragma unroll
        for (int o = 16; o > 0; o >>= 1) ls += __shfl_xor_sync(0xffffffffu, ls, o);
        if (lane == 0) wred[w] = ls;
        __syncthreads();
        if (w == 0) {
            float v = (lane < 10) ? wred[lane] : 0.f;
            #pragma unroll
            for (int o = 16; o > 0; o >>= 1) v += __shfl_xor_sync(0xffffffffu, v, o);
            if (lane == 0) wred[10] = v;
        }
        __syncthreads();
        float inv = 1.f / (wred[10] + 1e-10f);
        for (int p = tid; p < HWt; p += NTHR) {
            float al = exs[p] * inv;
            out[ALPHA_OFF + b * HWt + p] = al;
            out[ASUM_OFF + b * HWt + p] = al + asum[b * HWt + p];
        }
    }

    gridbar(1);

    // context: 256 threads (2 groups of 128), named bars per group; warps 8-9 exit
    if (tid < 256) {
        const int cr = tid >> 7, l = tid & 127;
        const int wq = (tid >> 5) & 3;
        for (int idx = blockIdx.x; idx < (Ct / 2) * Bt; idx += NCTA) {
            int b = idx / (Ct / 2);
            int cp = idx - b * (Ct / 2);
            int c = cp * 2 + cr;
            const float4* f = (const float4*)(cnn + (size_t)(b * Ct + c) * HWt);
            const float4* al = (const float4*)(out + ALPHA_OFF + b * HWt);
            float sdot = 0.f;
            #pragma unroll
            for (int i = 0; i < 2; ++i) {
                float4 a4 = al[l + i * 128], f4 = f[l + i * 128];
                sdot += a4.x * f4.x + a4.y * f4.y + a4.z * f4.z + a4.w * f4.w;
            }
            #pragma unroll
            for (int o = 16; o > 0; o >>= 1) sdot += __shfl_xor_sync(0xffffffffu, sdot, o);
            if (lane == 0) esm[cr * 4 + wq] = sdot;
            BARS(3 + cr, 128);
            if (l == 0)
                out[b * Ct + c] = esm[cr * 4] + esm[cr * 4 + 1] + esm[cr * 4 + 2] + esm[cr * 4 + 3];
            BARS(3 + cr, 128);
        }
    }
}

// ---------------- launch ----------------
extern "C" void kernel_launch(void* const* d_in, const int* in_sizes, int n_in,
                              void* d_out, int out_size) {
    const float* cnn    = (const float*)d_in[0];
    const float* hidden = (const float*)d_in[1];
    const float* asum   = (const float*)d_in[2];
    const float* mask   = (const float*)d_in[3];
    const float* Wh     = (const float*)d_in[4];
    const float* bh     = (const float*)d_in[5];
    const float* Wec    = (const float*)d_in[6];
    const float* bec    = (const float*)d_in[7];
    const float* Wac    = (const float*)d_in[8];
    const float* Waw    = (const float*)d_in[9];
    const float* Wv     = (const float*)d_in[10];
    const float* bv     = (const float*)d_in[11];
    float* out = (float*)d_out;

    cudaFuncSetAttribute(k_mma, cudaFuncAttributeMaxDynamicSharedMemorySize, SMEM_SZ);

    k_small<<<dim3(At, 2), 128>>>(Waw, Wac, hidden, Wh, bh, bec);   // 1
    k_wpack<<<dim3(NST, 4), 256>>>(Wec);                            // 2
    k_zero<<<1, 32>>>();                                            // 3
    k_mma<<<NCTA, NTHR, SMEM_SZ>>>(cnn, asum, mask, Wv, bv, out);   // 4 <- ncu slot
}

// round 12
// speedup vs baseline: 1.1797x; 1.1797x over previous
#include <cuda_runtime.h>
#include <cuda_fp16.h>
#include <stdint.h>
#include <math.h>

#define Bt 32
#define Ct 684
#define Ht 16
#define Wt 64
#define HWt 1024
#define HIDt 256
#define At 512
#define NPATCH 121
#define KCOMB 805
#define NST 13            // stages of k=64
#define NPOS 32768
#define NCTA 148
#define ALPHA_OFF (Bt*Ct)
#define ASUM_OFF  (Bt*Ct + Bt*HWt)

// tiles: X (128 pos x 64 k) fp16 = 16384 B ; W (256 a x 64 k) fp16 = 32768 B
#define XT 16384
#define WT 32768
#define STB (XT + WT)
#define NSLOT 4
#define SMEM_SZ (NSLOT*STB)    // 192 KB
#define NTILE 512              // interleaved: bx=tile>>1, by=tile&1

// ---------------- device scratch ----------------
__device__ __align__(1024) unsigned char g_X[(size_t)256 * NST * XT];   // 54.5 MB
__device__ __align__(1024) unsigned char g_W[(size_t)2 * NST * WT];     // 852 KB
__device__ float g_Weff[At * NPATCH];
__device__ float g_query[Bt * At];       // q + bh + bec folded
__device__ float g_Epart[2 * NPOS];
__device__ int g_cnt[2];

// ---------------- helpers ----------------
__device__ __forceinline__ uint32_t smem_u32(const void* p) {
    uint32_t a;
    asm("{ .reg .u64 t; cvta.to.shared.u64 t, %1; cvt.u32.u64 %0, t; }" : "=r"(a) : "l"(p));
    return a;
}
__device__ __forceinline__ void mb_init(uint32_t a, uint32_t c) {
    asm volatile("mbarrier.init.shared.b64 [%0], %1;" :: "r"(a), "r"(c) : "memory");
}
__device__ __forceinline__ void mb_arrive(uint32_t a) {
    asm volatile("mbarrier.arrive.shared.b64 _, [%0];" :: "r"(a) : "memory");
}
__device__ __forceinline__ void mb_tx(uint32_t a, uint32_t bytes) {
    asm volatile("mbarrier.arrive.expect_tx.shared.b64 _, [%0], %1;" :: "r"(a), "r"(bytes) : "memory");
}
__device__ __forceinline__ void mb_wait(uint32_t a, uint32_t par) {
    uint32_t d = 0;
    while (!d)
        asm volatile("{ .reg .pred p; mbarrier.try_wait.parity.acquire.cta.shared::cta.b64 p,[%1],%2,0x989680; selp.b32 %0,1,0,p; }"
                     : "=r"(d) : "r"(a), "r"(par) : "memory");
}
__device__ __forceinline__ void blkcp(uint32_t dst, const void* src, uint32_t bytes, uint32_t mbar) {
    asm volatile("cp.async.bulk.shared::cta.global.mbarrier::complete_tx::bytes [%0], [%1], %2, [%3];"
                 :: "r"(dst), "l"(src), "r"(bytes), "r"(mbar) : "memory");
}
#define BARS(id, n) asm volatile("bar.sync %0, %1;" :: "r"(id), "r"(n) : "memory")
#define LDMX4(r0,r1,r2,r3,addr) \
    asm volatile("ldmatrix.sync.aligned.m8n8.x4.shared.b16 {%0,%1,%2,%3}, [%4];" \
                 : "=r"(r0),"=r"(r1),"=r"(r2),"=r"(r3) : "r"(addr))
#define MMA(d,a,b) \
    asm volatile("mma.sync.aligned.m16n8k16.row.col.f32.f16.f16.f32 " \
                 "{%0,%1,%2,%3},{%4,%5,%6,%7},{%8,%9},{%0,%1,%2,%3};" \
                 : "+f"(d[0]),"+f"(d[1]),"+f"(d[2]),"+f"(d[3]) \
                 : "r"(a[0]),"r"(a[1]),"r"(a[2]),"r"(a[3]),"r"(b[0]),"r"(b[1]))

__device__ __forceinline__ uint32_t h2u(float v0, float v1) {
    __half2 h = __floats2half2_rn(v0, v1);
    return *(uint32_t*)&h;
}
__device__ __forceinline__ float ftanh(float x) {
    float e = __expf(2.0f * x);
    return 1.0f - __fdividef(2.0f, e + 1.0f);
}
__device__ __forceinline__ void gridbar(int ph) {
    __syncthreads();
    if (threadIdx.x == 0) {
        __threadfence();
        atomicAdd(&g_cnt[ph], 1);
        while (atomicAdd(&g_cnt[ph], 0) < NCTA) { }
        __threadfence();
    }
    __syncthreads();
}

// ---------------- prep: merged weff (y=0) + query (y=1) ----------------
__global__ void k_small(const float* __restrict__ Waw, const float* __restrict__ Wac,
                        const float* __restrict__ hidden, const float* __restrict__ Wh,
                        const float* __restrict__ bh, const float* __restrict__ bec) {
    if (blockIdx.y == 0) {
        int a = blockIdx.x, j = threadIdx.x;
        if (j >= NPATCH) return;
        float s = 0.f;
        for (int c = 0; c < At; ++c) s = fmaf(Waw[a * At + c], Wac[c * NPATCH + j], s);
        g_Weff[a * NPATCH + j] = s;
    } else {
        int b = blockIdx.x, tid = threadIdx.x;
        if (b >= Bt) return;
        __shared__ float h[HIDt];
        for (int k = tid; k < HIDt; k += 128) h[k] = hidden[b * HIDt + k];
        __syncthreads();
        for (int a = tid; a < At; a += 128) {
            const float* wr = Wh + a * HIDt;
            float s = 0.f;
            #pragma unroll 8
            for (int k = 0; k < HIDt; ++k) s = fmaf(wr[k], h[k], s);
            g_query[b * At + a] = s + bh[a] + bec[a];
        }
    }
}

// ---------------- prep: W tiles [ag][s] 256a x 64k fp16, SW128-swizzled ----------------
__global__ void k_wpack(const float* __restrict__ Wec) {
    __shared__ float sm[64][129];
    const int s = blockIdx.x, ag = blockIdx.y, tid = threadIdx.x;
    const int w = tid >> 5, lane = tid & 31;
    #pragma unroll 4
    for (int i = 0; i < 32; ++i) {
        int kk = lane + (i & 1) * 32;
        int a = w + (i >> 1) * 8;
        int k = s * 64 + kk, aa = ag * 128 + a;
        float v = 0.f;
        if (k < Ct) v = Wec[aa * Ct + k];
        else if (k < KCOMB) v = g_Weff[aa * NPATCH + (k - Ct)];
        sm[kk][a] = v;
    }
    __syncthreads();
    unsigned char* tile = g_W + ((size_t)((ag >> 1) * NST + s) << 15);
    const int rbase = (ag & 1) * 128;
    #pragma unroll
    for (int i = 0; i < 4; ++i) {
        int idx = i * 256 + tid;
        int r = idx >> 3, ch = idx & 7;
        uint32_t hv[4];
        #pragma unroll
        for (int j = 0; j < 4; ++j)
            hv[j] = h2u(sm[ch * 8 + 2 * j][r], sm[ch * 8 + 2 * j + 1][r]);
        int r2 = rbase + r;
        uint32_t off = r2 * 128 + ((ch ^ (r2 & 7)) << 4);
        *(uint4*)(tile + off) = make_uint4(hv[0], hv[1], hv[2], hv[3]);
    }
}

__global__ void k_zero() {
    if (threadIdx.x < 2) g_cnt[threadIdx.x] = 0;
}

// ---------------- prep: X tiles [pg][s] 128pos x 64k fp16, SW128-swizzled ----------------
__global__ void k_xprep(const float* __restrict__ cnn, const float* __restrict__ asum) {
    __shared__ float sm[64][129];
    const int s = blockIdx.x, pg = blockIdx.y, tid = threadIdx.x;
    const int b = pg >> 3;
    #pragma unroll
    for (int i = 0; i < 32; ++i) {
        int idx = i * 256 + tid;
        int kr = idx >> 7, p = idx & 127;
        int posb = (pg & 7) * 128 + p;
        int k = s * 64 + kr;
        float v = 0.f;
        if (k < Ct) {
            v = cnn[(size_t)b * (Ct * HWt) + k * HWt + posb];
        } else if (k < KCOMB) {
            int j = k - Ct;
            int hh = (posb >> 6) + j / 11 - 5;
            int ww = (posb & 63) + j % 11 - 5;
            if (hh >= 0 && hh < Ht && ww >= 0 && ww < Wt) v = asum[b * HWt + hh * Wt + ww];
        }
        sm[kr][p] = v;
    }
    __syncthreads();
    unsigned char* tile = g_X + ((size_t)(pg * NST + s) << 14);
    #pragma unroll
    for (int i = 0; i < 4; ++i) {
        int idx = i * 256 + tid;
        int r = idx >> 3, ch = idx & 7;
        uint32_t hv[4];
        #pragma unroll
        for (int j = 0; j < 4; ++j)
            hv[j] = h2u(sm[ch * 8 + 2 * j][r], sm[ch * 8 + 2 * j + 1][r]);
        uint32_t off = r * 128 + ((ch ^ (r & 7)) << 4);
        *(uint4*)(tile + off) = make_uint4(hv[0], hv[1], hv[2], hv[3]);
    }
}

// ---------------- main: persistent GEMM (R8 ring) + fused softmax/context tails ----------------
__global__ __launch_bounds__(256, 1)
void k_mma(const float* __restrict__ cnn, const float* __restrict__ asum,
           const float* __restrict__ mask, const float* __restrict__ Wv,
           const float* __restrict__ bv, float* __restrict__ out) {
    extern __shared__ char dsm[];
    __shared__ float qs[256], ws[256], esm[512];
    __shared__ __align__(8) uint64_t mbars[2 * NSLOT];
    const uint32_t sb = smem_u32(dsm);
    const uint32_t mbF = smem_u32(&mbars[0]);
    const uint32_t mbE = mbF + 8 * NSLOT;
    const int tid = threadIdx.x, lane = tid & 31, w = tid >> 5;
    const int wm = w >> 2, wn = w & 3;

    if (tid == 0)
        for (int i = 0; i < NSLOT; ++i) { mb_init(mbF + 8 * i, 1); mb_init(mbE + 8 * i, 1); }
    __syncthreads();

    int tiles[4], ntiles = 0;
    for (int t = blockIdx.x; t < NTILE; t += NCTA) tiles[ntiles++] = t;
    const int total = ntiles * NST;

    auto issue = [&](int gs) {
        int ti = gs / NST, s = gs - ti * NST;
        int tile = tiles[ti];
        int bx = tile >> 1, by = tile & 1;
        int slot = gs & (NSLOT - 1), u = gs >> 2;
        mb_wait(mbE + 8 * slot, 1 ^ (u & 1));
        uint32_t fb = mbF + 8 * slot;
        mb_tx(fb, STB);
        blkcp(sb + slot * STB, g_X + ((size_t)(bx * NST + s) << 14), XT, fb);
        blkcp(sb + slot * STB + XT, g_W + ((size_t)(by * NST + s) << 15), WT, fb);
    };

    if (tid == 0)
        for (int gs = 0; gs < 3 && gs < total; ++gs) issue(gs);

    int gs = 0;
    for (int ti = 0; ti < ntiles; ++ti) {
        const int tile = tiles[ti];
        const int bx = tile >> 1, by = tile & 1;
        const int pos0 = bx * 128, a0 = by * 256, b = bx >> 3;

        float acc[4][8][4];
        #pragma unroll
        for (int mt = 0; mt < 4; ++mt)
            #pragma unroll
            for (int nt = 0; nt < 8; ++nt)
                #pragma unroll
                for (int r = 0; r < 4; ++r) acc[mt][nt][r] = 0.f;

        for (int s = 0; s < NST; ++s, ++gs) {
            if (tid == 0 && gs + 3 < total) issue(gs + 3);
            const int slot = gs & (NSLOT - 1), u = gs >> 2;
            mb_wait(mbF + 8 * slot, u & 1);

            const uint32_t xb = sb + slot * STB;
            const uint32_t wb = xb + XT;

            #pragma unroll
            for (int ks = 0; ks < 4; ++ks) {
                uint32_t bf[8][2];
                const int browb = wn * 64 + (lane & 7) + ((lane >> 4) & 1) * 8;
                const int bc = 2 * ks + ((lane >> 3) & 1);
                #pragma unroll
                for (int np = 0; np < 4; ++np) {
                    int r = browb + np * 16;
                    uint32_t boff = r * 128 + ((bc ^ (r & 7)) << 4);
                    LDMX4(bf[np*2][0], bf[np*2][1], bf[np*2+1][0], bf[np*2+1][1], wb + boff);
                }
                const int arow = wm * 64 + (lane & 15);
                const int ac = 2 * ks + (lane >> 4);
                #pragma unroll
                for (int mt = 0; mt < 4; ++mt) {
                    int r = arow + mt * 16;
                    uint32_t aoff = r * 128 + ((ac ^ (r & 7)) << 4);
                    uint32_t af[4];
                    LDMX4(af[0], af[1], af[2], af[3], xb + aoff);
                    #pragma unroll
                    for (int nt = 0; nt < 8; ++nt)
                        MMA(acc[mt][nt], af, bf[nt]);
                }
            }
            __syncthreads();
            if (tid == 0) mb_arrive(mbE + 8 * slot);
        }

        // epilogue: e[pos] = sum_a Wv[a]*tanh(acc + q[b][a])
        qs[tid] = g_query[b * At + a0 + tid];
        ws[tid] = Wv[a0 + tid];
        __syncthreads();

        #pragma unroll
        for (int mt = 0; mt < 4; ++mt) {
            float er0 = 0.f, er1 = 0.f;
            #pragma unroll
            for (int nt = 0; nt < 8; ++nt) {
                int col = wn * 64 + nt * 8 + (lane & 3) * 2;
                float q0 = qs[col], q1 = qs[col + 1];
                float w0 = ws[col], w1 = ws[col + 1];
                er0 = fmaf(w0, ftanh(acc[mt][nt][0] + q0), er0);
                er0 = fmaf(w1, ftanh(acc[mt][nt][1] + q1), er0);
                er1 = fmaf(w0, ftanh(acc[mt][nt][2] + q0), er1);
                er1 = fmaf(w1, ftanh(acc[mt][nt][3] + q1), er1);
            }
            er0 += __shfl_xor_sync(0xffffffffu, er0, 1);
            er0 += __shfl_xor_sync(0xffffffffu, er0, 2);
            er1 += __shfl_xor_sync(0xffffffffu, er1, 1);
            er1 += __shfl_xor_sync(0xffffffffu, er1, 2);
            if ((lane & 3) == 0) {
                int r = wm * 64 + mt * 16 + (lane >> 2);
                esm[r * 4 + wn] = er0;
                esm[(r + 8) * 4 + wn] = er1;
            }
        }
        __syncthreads();
        if (tid < 128)
            g_Epart[by * NPOS + pos0 + tid] =
                esm[tid * 4] + esm[tid * 4 + 1] + esm[tid * 4 + 2] + esm[tid * 4 + 3];
        __syncthreads();
    }

    // ==== all Epart written ====
    gridbar(0);

    // softmax per batch (CTAs 0-31); per-batch max (normalization-invariant)
    if (blockIdx.x < Bt) {
        const int b = blockIdx.x;
        float* exs = (float*)dsm;
        float bvv = bv[0];
        float ev[4], m = -1e30f;
        #pragma unroll
        for (int i = 0; i < 4; ++i) {
            int p = tid + i * 256;
            float e = bvv + g_Epart[b * HWt + p] + g_Epart[NPOS + b * HWt + p];
            ev[i] = e; m = fmaxf(m, e);
        }
        esm[tid] = m; __syncthreads();
        for (int s2 = 128; s2 > 0; s2 >>= 1) { if (tid < s2) esm[tid] = fmaxf(esm[tid], esm[tid + s2]); __syncthreads(); }
        m = esm[0];
        __syncthreads();
        float ls = 0.f;
        #pragma unroll
        for (int i = 0; i < 4; ++i) {
            int p = tid + i * 256;
            float v = expf(ev[i] - m) * mask[b * HWt + p];
            exs[p] = v; ls += v;
        }
        esm[tid] = ls; __syncthreads();
        for (int s2 = 128; s2 > 0; s2 >>= 1) { if (tid < s2) esm[tid] += esm[tid + s2]; __syncthreads(); }
        float inv = 1.f / (esm[0] + 1e-10f);
        #pragma unroll
        for (int i = 0; i < 4; ++i) {
            int p = tid + i * 256;
            float al = exs[p] * inv;
            out[ALPHA_OFF + b * HWt + p] = al;
            out[ASUM_OFF + b * HWt + p] = al + asum[b * HWt + p];
        }
    }

    gridbar(1);

    // context: full chip, 2 c-rows per block-iteration (alpha hot in L2)
    const int cr = tid >> 7, l = tid & 127;
    const int wq = (tid >> 5) & 3;
    for (int idx = blockIdx.x; idx < (Ct / 2) * Bt; idx += NCTA) {
        int b = idx / (Ct / 2);
        int cp = idx - b * (Ct / 2);
        int c = cp * 2 + cr;
        const float4* f = (const float4*)(cnn + (size_t)(b * Ct + c) * HWt);
        const float4* al = (const float4*)(out + ALPHA_OFF + b * HWt);
        float sdot = 0.f;
        #pragma unroll
        for (int i = 0; i < 2; ++i) {
            float4 a4 = al[l + i * 128], f4 = f[l + i * 128];
            sdot += a4.x * f4.x + a4.y * f4.y + a4.z * f4.z + a4.w * f4.w;
        }
        #pragma unroll
        for (int o = 16; o > 0; o >>= 1) sdot += __shfl_xor_sync(0xffffffffu, sdot, o);
        if (lane == 0) esm[cr * 4 + wq] = sdot;
        BARS(3 + cr, 128);
        if (l == 0)
            out[b * Ct + c] = esm[cr * 4] + esm[cr * 4 + 1] + esm[cr * 4 + 2] + esm[cr * 4 + 3];
        BARS(3 + cr, 128);
    }
}

// ---------------- launch ----------------
extern "C" void kernel_launch(void* const* d_in, const int* in_sizes, int n_in,
                              void* d_out, int out_size) {
    const float* cnn    = (const float*)d_in[0];
    const float* hidden = (const float*)d_in[1];
    const float* asum   = (const float*)d_in[2];
    const float* mask   = (const float*)d_in[3];
    const float* Wh     = (const float*)d_in[4];
    const float* bh     = (const float*)d_in[5];
    const float* Wec    = (const float*)d_in[6];
    const float* bec    = (const float*)d_in[7];
    const float* Wac    = (const float*)d_in[8];
    const float* Waw    = (const float*)d_in[9];
    const float* Wv     = (const float*)d_in[10];
    const float* bv     = (const float*)d_in[11];
    float* out = (float*)d_out;

    cudaFuncSetAttribute(k_mma, cudaFuncAttributeMaxDynamicSharedMemorySize, SMEM_SZ);

    k_small<<<dim3(At, 2), 128>>>(Waw, Wac, hidden, Wh, bh, bec);   // 1
    k_wpack<<<dim3(NST, 4), 256>>>(Wec);                            // 2
    k_zero<<<1, 32>>>();                                            // 3
    k_xprep<<<dim3(NST, 256), 256>>>(cnn, asum);                    // 4
    k_mma<<<NCTA, 256, SMEM_SZ>>>(cnn, asum, mask, Wv, bv, out);    // 5
}

// round 14
// speedup vs baseline: 1.2871x; 1.0910x over previous
#include <cuda_runtime.h>
#include <cuda_fp16.h>
#include <stdint.h>
#include <math.h>

#define Bt 32
#define Ct 684
#define Ht 16
#define Wt 64
#define HWt 1024
#define HIDt 256
#define At 512
#define NPATCH 121
#define KCOMB 805
#define NST 13
#define NPOS 32768
#define NCTA 148
#define ALPHA_OFF (Bt*Ct)
#define ASUM_OFF  (Bt*Ct + Bt*HWt)

// dynamic smem: Xbuf[2]@0 (32768) | Wbuf[2]@32768 (65536) | stg[3]@98304 (3*33792) | asum@199680 (4096)
#define XB  0
#define WB  32768
#define STG 98304
#define STGB 33792
#define ASM 199680
#define SMEM_SZ 203776
#define XT 16384
#define WT 32768
#define STGP 132
#define NTILE 512

// ---------------- device scratch ----------------
__device__ __align__(1024) unsigned char g_W[(size_t)2 * NST * WT];
__device__ float g_Weff[At * NPATCH];
__device__ float g_query[Bt * At];
__device__ float g_Epart[2 * NPOS];
__device__ int g_cnt[2];

// ---------------- helpers ----------------
__device__ __forceinline__ uint32_t smem_u32(const void* p) {
    uint32_t a;
    asm("{ .reg .u64 t; cvta.to.shared.u64 t, %1; cvt.u32.u64 %0, t; }" : "=r"(a) : "l"(p));
    return a;
}
__device__ __forceinline__ void mb_init(uint32_t a, uint32_t c) {
    asm volatile("mbarrier.init.shared.b64 [%0], %1;" :: "r"(a), "r"(c) : "memory");
}
__device__ __forceinline__ void mb_tx(uint32_t a, uint32_t bytes) {
    asm volatile("mbarrier.arrive.expect_tx.shared.b64 _, [%0], %1;" :: "r"(a), "r"(bytes) : "memory");
}
__device__ __forceinline__ void mb_wait(uint32_t a, uint32_t par) {
    uint32_t d = 0;
    while (!d)
        asm volatile("{ .reg .pred p; mbarrier.try_wait.parity.acquire.cta.shared::cta.b64 p,[%1],%2,0x989680; selp.b32 %0,1,0,p; }"
                     : "=r"(d) : "r"(a), "r"(par) : "memory");
}
__device__ __forceinline__ void blkcp(uint32_t dst, const void* src, uint32_t bytes, uint32_t mbar) {
    asm volatile("cp.async.bulk.shared::cta.global.mbarrier::complete_tx::bytes [%0], [%1], %2, [%3];"
                 :: "r"(dst), "l"(src), "r"(bytes), "r"(mbar) : "memory");
}
__device__ __forceinline__ void cpa16(uint32_t dst, const void* src) {
    asm volatile("cp.async.cg.shared.global [%0], [%1], 16;" :: "r"(dst), "l"(src));
}
#define BARS(id, n) asm volatile("bar.sync %0, %1;" :: "r"(id), "r"(n) : "memory")
#define LDMX4(r0,r1,r2,r3,addr) \
    asm volatile("ldmatrix.sync.aligned.m8n8.x4.shared.b16 {%0,%1,%2,%3}, [%4];" \
                 : "=r"(r0),"=r"(r1),"=r"(r2),"=r"(r3) : "r"(addr))
#define MMA(d,a,b) \
    asm volatile("mma.sync.aligned.m16n8k16.row.col.f32.f16.f16.f32 " \
                 "{%0,%1,%2,%3},{%4,%5,%6,%7},{%8,%9},{%0,%1,%2,%3};" \
                 : "+f"(d[0]),"+f"(d[1]),"+f"(d[2]),"+f"(d[3]) \
                 : "r"(a[0]),"r"(a[1]),"r"(a[2]),"r"(a[3]),"r"(b[0]),"r"(b[1]))

__device__ __forceinline__ uint32_t h2u(float v0, float v1) {
    __half2 h = __floats2half2_rn(v0, v1);
    return *(uint32_t*)&h;
}
__device__ __forceinline__ float ftanh(float x) {
    float e = __expf(2.0f * x);
    return 1.0f - __fdividef(2.0f, e + 1.0f);
}
__device__ __forceinline__ void gridbar(int ph) {
    __syncthreads();
    if (threadIdx.x == 0) {
        __threadfence();
        atomicAdd(&g_cnt[ph], 1);
        while (atomicAdd(&g_cnt[ph], 0) < NCTA) { }
        __threadfence();
    }
    __syncthreads();
}

// ---------------- prep: merged weff (y=0) + query (y=1) ----------------
__global__ void k_small(const float* __restrict__ Waw, const float* __restrict__ Wac,
                        const float* __restrict__ hidden, const float* __restrict__ Wh,
                        const float* __restrict__ bh, const float* __restrict__ bec) {
    if (blockIdx.y == 0) {
        int a = blockIdx.x, j = threadIdx.x;
        if (j >= NPATCH) return;
        float s = 0.f;
        for (int c = 0; c < At; ++c) s = fmaf(Waw[a * At + c], Wac[c * NPATCH + j], s);
        g_Weff[a * NPATCH + j] = s;
    } else {
        int b = blockIdx.x, tid = threadIdx.x;
        if (b >= Bt) return;
        __shared__ float h[HIDt];
        for (int k = tid; k < HIDt; k += 128) h[k] = hidden[b * HIDt + k];
        __syncthreads();
        for (int a = tid; a < At; a += 128) {
            const float* wr = Wh + a * HIDt;
            float s = 0.f;
            #pragma unroll 8
            for (int k = 0; k < HIDt; ++k) s = fmaf(wr[k], h[k], s);
            g_query[b * At + a] = s + bh[a] + bec[a];
        }
    }
}

// ---------------- prep: W tiles [ag][s] 256a x 64k fp16, SW128-swizzled ----------------
__global__ void k_wpack(const float* __restrict__ Wec) {
    __shared__ float sm[64][129];
    const int s = blockIdx.x, ag = blockIdx.y, tid = threadIdx.x;
    const int w = tid >> 5, lane = tid & 31;
    #pragma unroll 4
    for (int i = 0; i < 32; ++i) {
        int kk = lane + (i & 1) * 32;
        int a = w + (i >> 1) * 8;
        int k = s * 64 + kk, aa = ag * 128 + a;
        float v = 0.f;
        if (k < Ct) v = Wec[aa * Ct + k];
        else if (k < KCOMB) v = g_Weff[aa * NPATCH + (k - Ct)];
        sm[kk][a] = v;
    }
    __syncthreads();
    unsigned char* tile = g_W + ((size_t)((ag >> 1) * NST + s) << 15);
    const int rbase = (ag & 1) * 128;
    #pragma unroll
    for (int i = 0; i < 4; ++i) {
        int idx = i * 256 + tid;
        int r = idx >> 3, ch = idx & 7;
        uint32_t hv[4];
        #pragma unroll
        for (int j = 0; j < 4; ++j)
            hv[j] = h2u(sm[ch * 8 + 2 * j][r], sm[ch * 8 + 2 * j + 1][r]);
        int r2 = rbase + r;
        uint32_t off = r2 * 128 + ((ch ^ (r2 & 7)) << 4);
        *(uint4*)(tile + off) = make_uint4(hv[0], hv[1], hv[2], hv[3]);
    }
}

__global__ void k_zero() {
    if (threadIdx.x < 2) g_cnt[threadIdx.x] = 0;
}

// ---------------- main: persistent megakernel, staggered half-CTA convert (race-fixed) ----------------
__global__ __launch_bounds__(256, 1)
void k_mma(const float* __restrict__ cnn, const float* __restrict__ asum,
           const float* __restrict__ mask, const float* __restrict__ Wv,
           const float* __restrict__ bv, float* __restrict__ out) {
    extern __shared__ char dsm[];
    __shared__ float qs[256], ws[256], esm[512];
    __shared__ __align__(8) uint64_t mbars[2];
    const uint32_t sb = smem_u32(dsm);
    const uint32_t mbF = smem_u32(&mbars[0]);
    float* asm_s = (float*)(dsm + ASM);
    const int tid = threadIdx.x, lane = tid & 31, w = tid >> 5;
    const int wm = w >> 2, wn = w & 3;
    const int half = w >> 2;
    const int htid = tid & 127;

    if (tid == 0) { mb_init(mbF, 1); mb_init(mbF + 8, 1); }
    __syncthreads();

    int tiles[4], ntiles = 0;
    for (int t = blockIdx.x; t < NTILE; t += NCTA) tiles[ntiles++] = t;
    const int total = ntiles * NST;

    auto cpaX = [&](int g) {
        int ti2 = g / NST, s2 = g - ti2 * NST, bx = tiles[ti2] >> 1;
        int b2 = bx >> 3, pos0b = (bx & 7) * 128;
        const float* src = cnn + ((size_t)b2 * Ct + s2 * 64) * HWt + pos0b;
        uint32_t dstb = sb + STG + (g % 3) * STGB;
        #pragma unroll
        for (int i = 0; i < 8; ++i) {
            int id = i * 256 + tid;
            int row = id >> 5, c = id & 31;
            if (s2 * 64 + row < Ct)
                cpa16(dstb + row * (STGP * 4) + c * 16,
                      (const char*)(src + (size_t)row * HWt) + c * 16);
        }
    };

    auto convert = [&](int g, int lid, int iters, int stride) {
        int ti2 = g / NST, s2 = g - ti2 * NST, bx = tiles[ti2] >> 1;
        int pos0b = (bx & 7) * 128;
        float* stgf = (float*)(dsm + STG + (g % 3) * STGB);
        char* dx = dsm + XB + (g & 1) * XT;
        const int k0 = s2 * 64;
        if (k0 + 63 < Ct) {
            for (int i = 0; i < iters; ++i) {
                int idx = i * stride + lid;
                int r = idx & 127, ch = idx >> 7;
                uint32_t hv[4];
                #pragma unroll
                for (int j = 0; j < 4; ++j)
                    hv[j] = h2u(stgf[(ch * 8 + 2 * j) * STGP + r],
                                stgf[(ch * 8 + 2 * j + 1) * STGP + r]);
                uint32_t off = r * 128 + ((ch ^ (r & 7)) << 4);
                *(uint4*)(dx + off) = make_uint4(hv[0], hv[1], hv[2], hv[3]);
            }
        } else {
            for (int i = 0; i < iters; ++i) {
                int idx = i * stride + lid;
                int r = idx & 127, ch = idx >> 7;
                float v[8];
                #pragma unroll
                for (int jj = 0; jj < 8; ++jj) {
                    int kk = ch * 8 + jj, k = k0 + kk;
                    float x = 0.f;
                    if (k < Ct) {
                        x = stgf[kk * STGP + r];
                    } else if (k < KCOMB) {
                        int j = k - Ct;
                        int pos = pos0b + r;
                        int hh = (pos >> 6) + j / 11 - 5;
                        int ww = (pos & 63) + j % 11 - 5;
                        if (hh >= 0 && hh < Ht && ww >= 0 && ww < Wt) x = asm_s[hh * Wt + ww];
                    }
                    v[jj] = x;
                }
                uint32_t hv[4];
                #pragma unroll
                for (int j = 0; j < 4; ++j) hv[j] = h2u(v[2 * j], v[2 * j + 1]);
                uint32_t off = r * 128 + ((ch ^ (r & 7)) << 4);
                *(uint4*)(dx + off) = make_uint4(hv[0], hv[1], hv[2], hv[3]);
            }
        }
    };

    // ---- prologue: W(0), staging(0,1), asum, convert(0) ----
    {
        int by0 = tiles[0] & 1, b0 = (tiles[0] >> 1) >> 3;
        if (tid == 0) {
            mb_tx(mbF, WT);
            blkcp(sb + WB, g_W + ((size_t)(by0 * NST) << 15), WT, mbF);
        }
        cpaX(0);
        asm volatile("cp.async.commit_group;" ::: "memory");
        if (total > 1) cpaX(1);
        asm volatile("cp.async.commit_group;" ::: "memory");
        for (int i = tid; i < HWt; i += 256) asm_s[i] = asum[b0 * HWt + i];
        asm volatile("cp.async.wait_group 1;" ::: "memory");
        __syncthreads();
        convert(0, tid, 4, 256);
        __syncthreads();
    }

    float acc[4][8][4];
    #pragma unroll
    for (int mt = 0; mt < 4; ++mt)
        #pragma unroll
        for (int nt = 0; nt < 8; ++nt)
            #pragma unroll
            for (int r = 0; r < 4; ++r) acc[mt][nt][r] = 0.f;

    int ti = 0, s = 0;
    for (int g = 0; g < total; ++g) {
        // X fetch for g+2 into stg[(g+2)%3]
        if (g + 2 < total) cpaX(g + 2);
        asm volatile("cp.async.commit_group;" ::: "memory");
        asm volatile("cp.async.wait_group 1;" ::: "memory");   // own groups <= g+1 complete
        __syncthreads();   // joins MMA(g-1) of ALL warps; staging(g+1) visible; Wbuf/Xbuf[(g+1)&1] free
        // W issue for g+1 AFTER the sync: previous reader (MMA(g-1)) of Wbuf[(g+1)&1] is joined
        if (tid == 0 && g + 1 < total) {
            int nti = (g + 1) / NST, ns2 = (g + 1) - nti * NST, nby = tiles[nti] & 1;
            uint32_t fb = mbF + ((g + 1) & 1) * 8;
            mb_tx(fb, WT);
            blkcp(sb + WB + ((g + 1) & 1) * WT, g_W + ((size_t)(nby * NST + ns2) << 15), WT, fb);
        }
        // staggered convert: one half converts g+1, other half goes straight to MMA(g)
        if (g + 1 < total && half == ((g + 1) & 1)) convert(g + 1, htid, 8, 128);
        // MMA stage g
        mb_wait(mbF + (g & 1) * 8, (g >> 1) & 1);
        {
            const uint32_t xb = sb + XB + (g & 1) * XT;
            const uint32_t wb = sb + WB + (g & 1) * WT;
            #pragma unroll
            for (int ks = 0; ks < 4; ++ks) {
                uint32_t bf[8][2];
                const int browb = wn * 64 + (lane & 7) + ((lane >> 4) & 1) * 8;
                const int bc = 2 * ks + ((lane >> 3) & 1);
                #pragma unroll
                for (int np = 0; np < 4; ++np) {
                    int r = browb + np * 16;
                    uint32_t boff = r * 128 + ((bc ^ (r & 7)) << 4);
                    LDMX4(bf[np*2][0], bf[np*2][1], bf[np*2+1][0], bf[np*2+1][1], wb + boff);
                }
                const int arow = wm * 64 + (lane & 15);
                const int ac = 2 * ks + (lane >> 4);
                #pragma unroll
                for (int mt = 0; mt < 4; ++mt) {
                    int r = arow + mt * 16;
                    uint32_t aoff = r * 128 + ((ac ^ (r & 7)) << 4);
                    uint32_t af[4];
                    LDMX4(af[0], af[1], af[2], af[3], xb + aoff);
                    #pragma unroll
                    for (int nt = 0; nt < 8; ++nt)
                        MMA(acc[mt][nt], af, bf[nt]);
                }
            }
        }

        if (++s == NST) {
            // ---- epilogue for tile ti ----
            const int bx = tiles[ti] >> 1, by = tiles[ti] & 1;
            const int pos0 = bx * 128, a0 = by * 256, b = bx >> 3;
            __syncthreads();
            qs[tid] = g_query[b * At + a0 + tid];
            ws[tid] = Wv[a0 + tid];
            __syncthreads();
            #pragma unroll
            for (int mt = 0; mt < 4; ++mt) {
                float er0 = 0.f, er1 = 0.f;
                #pragma unroll
                for (int nt = 0; nt < 8; ++nt) {
                    int col = wn * 64 + nt * 8 + (lane & 3) * 2;
                    float q0 = qs[col], q1 = qs[col + 1];
                    float w0 = ws[col], w1 = ws[col + 1];
                    er0 = fmaf(w0, ftanh(acc[mt][nt][0] + q0), er0);
                    er0 = fmaf(w1, ftanh(acc[mt][nt][1] + q1), er0);
                    er1 = fmaf(w0, ftanh(acc[mt][nt][2] + q0), er1);
                    er1 = fmaf(w1, ftanh(acc[mt][nt][3] + q1), er1);
                }
                er0 += __shfl_xor_sync(0xffffffffu, er0, 1);
                er0 += __shfl_xor_sync(0xffffffffu, er0, 2);
                er1 += __shfl_xor_sync(0xffffffffu, er1, 1);
                er1 += __shfl_xor_sync(0xffffffffu, er1, 2);
                if ((lane & 3) == 0) {
                    int r = wm * 64 + mt * 16 + (lane >> 2);
                    esm[r * 4 + wn] = er0;
                    esm[(r + 8) * 4 + wn] = er1;
                }
            }
            __syncthreads();
            if (tid < 128)
                g_Epart[by * NPOS + pos0 + tid] =
                    esm[tid * 4] + esm[tid * 4 + 1] + esm[tid * 4 + 2] + esm[tid * 4 + 3];
            #pragma unroll
            for (int mt = 0; mt < 4; ++mt)
                #pragma unroll
                for (int nt = 0; nt < 8; ++nt)
                    #pragma unroll
                    for (int r = 0; r < 4; ++r) acc[mt][nt][r] = 0.f;
            if (ti + 1 < ntiles) {
                int nb = (tiles[ti + 1] >> 1) >> 3;
                for (int i = tid; i < HWt; i += 256) asm_s[i] = asum[nb * HWt + i];
            }
            s = 0; ++ti;
        }
    }

    // ==== all Epart written ====
    gridbar(0);

    // softmax per batch (CTAs 0-31); per-batch max (normalization-invariant)
    if (blockIdx.x < Bt) {
        const int b = blockIdx.x;
        float* exs = (float*)dsm;
        float bvv = bv[0];
        float ev[4], m = -1e30f;
        #pragma unroll
        for (int i = 0; i < 4; ++i) {
            int p = tid + i * 256;
            float e = bvv + g_Epart[b * HWt + p] + g_Epart[NPOS + b * HWt + p];
            ev[i] = e; m = fmaxf(m, e);
        }
        esm[tid] = m; __syncthreads();
        for (int s2 = 128; s2 > 0; s2 >>= 1) { if (tid < s2) esm[tid] = fmaxf(esm[tid], esm[tid + s2]); __syncthreads(); }
        m = esm[0];
        __syncthreads();
        float ls = 0.f;
        #pragma unroll
        for (int i = 0; i < 4; ++i) {
            int p = tid + i * 256;
            float v = expf(ev[i] - m) * mask[b * HWt + p];
            exs[p] = v; ls += v;
        }
        esm[tid] = ls; __syncthreads();
        for (int s2 = 128; s2 > 0; s2 >>= 1) { if (tid < s2) esm[tid] += esm[tid + s2]; __syncthreads(); }
        float inv = 1.f / (esm[0] + 1e-10f);
        #pragma unroll
        for (int i = 0; i < 4; ++i) {
            int p = tid + i * 256;
            float al = exs[p] * inv;
            out[ALPHA_OFF + b * HWt + p] = al;
            out[ASUM_OFF + b * HWt + p] = al + asum[b * HWt + p];
        }
    }

    gridbar(1);

    // context: full chip, 2 c-rows per block-iteration (alpha hot in L2)
    {
        const int cr = tid >> 7, l = tid & 127;
        const int wq = (tid >> 5) & 3;
        for (int idx = blockIdx.x; idx < (Ct / 2) * Bt; idx += NCTA) {
            int b = idx / (Ct / 2);
            int cp = idx - b * (Ct / 2);
            int c = cp * 2 + cr;
            const float4* f = (const float4*)(cnn + (size_t)(b * Ct + c) * HWt);
            const float4* al = (const float4*)(out + ALPHA_OFF + b * HWt);
            float sdot = 0.f;
            #pragma unroll
            for (int i = 0; i < 2; ++i) {
                float4 a4 = al[l + i * 128], f4 = f[l + i * 128];
                sdot += a4.x * f4.x + a4.y * f4.y + a4.z * f4.z + a4.w * f4.w;
            }
            #pragma unroll
            for (int o = 16; o > 0; o >>= 1) sdot += __shfl_xor_sync(0xffffffffu, sdot, o);
            if (lane == 0) esm[cr * 4 + wq] = sdot;
            BARS(3 + cr, 128);
            if (l == 0)
                out[b * Ct + c] = esm[cr * 4] + esm[cr * 4 + 1] + esm[cr * 4 + 2] + esm[cr * 4 + 3];
            BARS(3 + cr, 128);
        }
    }
}

// ---------------- launch ----------------
extern "C" void kernel_launch(void* const* d_in, const int* in_sizes, int n_in,
                              void* d_out, int out_size) {
    const float* cnn    = (const float*)d_in[0];
    const float* hidden = (const float*)d_in[1];
    const float* asum   = (const float*)d_in[2];
    const float* mask   = (const float*)d_in[3];
    const float* Wh     = (const float*)d_in[4];
    const float* bh     = (const float*)d_in[5];
    const float* Wec    = (const float*)d_in[6];
    const float* bec    = (const float*)d_in[7];
    const float* Wac    = (const float*)d_in[8];
    const float* Waw    = (const float*)d_in[9];
    const float* Wv     = (const float*)d_in[10];
    const float* bv     = (const float*)d_in[11];
    float* out = (float*)d_out;

    cudaFuncSetAttribute(k_mma, cudaFuncAttributeMaxDynamicSharedMemorySize, SMEM_SZ);

    k_small<<<dim3(At, 2), 128>>>(Waw, Wac, hidden, Wh, bh, bec);   // 1
    k_wpack<<<dim3(NST, 4), 256>>>(Wec);                            // 2
    k_zero<<<1, 32>>>();                                            // 3
    k_mma<<<NCTA, 256, SMEM_SZ>>>(cnn, asum, mask, Wv, bv, out);    // 4 <- ncu slot
}